// round 1
// baseline (speedup 1.0000x reference)
#include <cuda_runtime.h>

#define N_TOK   2048
#define D_MODEL 1024
#define D_INT   512
#define NE      8
#define NPAIR   (N_TOK * 2)

// ---- scratch (allocation-free: __device__ globals) ----
__device__ int   g_off[NE + 1];
__device__ int   g_cur[NE];
__device__ int   g_pair[NPAIR];                      // pair ids, grouped by expert
__device__ float g_a[(size_t)NPAIR * D_INT];         // gated activations, 8 MB
__device__ float g_slot[(size_t)NPAIR * D_MODEL];    // per-slot expert outputs, 16 MB

// ---------------- setup kernels ----------------
__global__ void k_offsets(const int* __restrict__ counts) {
    int o = 0;
    g_off[0] = 0;
    for (int e = 0; e < NE; e++) {
        o += counts[e];
        g_off[e + 1] = o;
        g_cur[e] = g_off[e];
    }
}

__global__ void k_scatter(const int* __restrict__ indices) {
    int p = blockIdx.x * blockDim.x + threadIdx.x;
    if (p >= NPAIR) return;
    int e = indices[p];                 // indices is (N_TOK, 2) row-major; p = t*2+k
    int pos = atomicAdd(&g_cur[e], 1);
    g_pair[pos] = p;
}

// ---------------- fc1 + gated SiLU ----------------
// Per expert segment: A = gathered x rows [M x 1024], W = fc1[e] [(1024) x 1024].
// Computes y = A * Wy^T, z = A * Wz^T (Wy rows 0..511, Wz rows 512..1023),
// writes a = y * z * sigmoid(z) into g_a (rows in expert-sorted order).
// Tile: BM=128, BN=64 (per gate), BK=16, TM=8, TN=4, 256 threads.
__global__ __launch_bounds__(256) void k_fc1(const float* __restrict__ x,
                                             const float* __restrict__ fc1w) {
    int e = blockIdx.z;
    int seg_beg = g_off[e];
    int seg_end = g_off[e + 1];
    int m0 = blockIdx.y * 128;
    int rows = seg_end - seg_beg - m0;
    if (rows <= 0) return;
    if (rows > 128) rows = 128;
    int n0 = blockIdx.x * 64;

    const float* W = fc1w + (size_t)e * (2 * D_INT) * D_MODEL;

    __shared__ float As[16][132];   // padded, float4-aligned rows (132*4=528=16*33)
    __shared__ float Bys[16][64];
    __shared__ float Bzs[16][64];
    __shared__ int   toks[128];

    int tid = threadIdx.x;
    if (tid < 128)
        toks[tid] = (tid < rows) ? (g_pair[seg_beg + m0 + tid] >> 1) : 0;
    __syncthreads();

    float accy[8][4], accz[8][4];
#pragma unroll
    for (int i = 0; i < 8; i++)
#pragma unroll
        for (int j = 0; j < 4; j++) { accy[i][j] = 0.f; accz[i][j] = 0.f; }

    int tx = tid & 15, ty = tid >> 4;
    int ar  = tid >> 1;           // A row, 2 float4 per thread
    int ac0 = (tid & 1) * 8;      // A col base
    int brn = tid >> 2;           // B row (n), 1 float4 per thread
    int bc  = (tid & 3) * 4;

    const float* xrow = x + (size_t)toks[ar] * D_MODEL + ac0;

    for (int k0 = 0; k0 < D_MODEL; k0 += 16) {
        float4 a0, a1;
        if (ar < rows) {
            a0 = *(const float4*)(xrow + k0);
            a1 = *(const float4*)(xrow + k0 + 4);
        } else {
            a0 = make_float4(0.f, 0.f, 0.f, 0.f);
            a1 = a0;
        }
        As[ac0 + 0][ar] = a0.x; As[ac0 + 1][ar] = a0.y;
        As[ac0 + 2][ar] = a0.z; As[ac0 + 3][ar] = a0.w;
        As[ac0 + 4][ar] = a1.x; As[ac0 + 5][ar] = a1.y;
        As[ac0 + 6][ar] = a1.z; As[ac0 + 7][ar] = a1.w;

        float4 by = *(const float4*)(W + (size_t)(n0 + brn) * D_MODEL + k0 + bc);
        Bys[bc + 0][brn] = by.x; Bys[bc + 1][brn] = by.y;
        Bys[bc + 2][brn] = by.z; Bys[bc + 3][brn] = by.w;

        float4 bz = *(const float4*)(W + (size_t)(D_INT + n0 + brn) * D_MODEL + k0 + bc);
        Bzs[bc + 0][brn] = bz.x; Bzs[bc + 1][brn] = bz.y;
        Bzs[bc + 2][brn] = bz.z; Bzs[bc + 3][brn] = bz.w;

        __syncthreads();

#pragma unroll
        for (int kk = 0; kk < 16; kk++) {
            float4 av0 = *(const float4*)&As[kk][ty * 8];
            float4 av1 = *(const float4*)&As[kk][ty * 8 + 4];
            float4 byv = *(const float4*)&Bys[kk][tx * 4];
            float4 bzv = *(const float4*)&Bzs[kk][tx * 4];
            float a[8] = {av0.x, av0.y, av0.z, av0.w, av1.x, av1.y, av1.z, av1.w};
            float byr[4] = {byv.x, byv.y, byv.z, byv.w};
            float bzr[4] = {bzv.x, bzv.y, bzv.z, bzv.w};
#pragma unroll
            for (int i = 0; i < 8; i++)
#pragma unroll
                for (int j = 0; j < 4; j++) {
                    accy[i][j] += a[i] * byr[j];
                    accz[i][j] += a[i] * bzr[j];
                }
        }
        __syncthreads();
    }

#pragma unroll
    for (int i = 0; i < 8; i++) {
        int m = ty * 8 + i;
        if (m < rows) {
            float* ap = g_a + (size_t)(seg_beg + m0 + m) * D_INT + n0 + tx * 4;
            float4 r;
            float z0 = accz[i][0], z1 = accz[i][1], z2 = accz[i][2], z3 = accz[i][3];
            r.x = accy[i][0] * z0 * (1.f / (1.f + __expf(-z0)));
            r.y = accy[i][1] * z1 * (1.f / (1.f + __expf(-z1)));
            r.z = accy[i][2] * z2 * (1.f / (1.f + __expf(-z2)));
            r.w = accy[i][3] * z3 * (1.f / (1.f + __expf(-z3)));
            *(float4*)ap = r;
        }
    }
}

// ---------------- fc2 ----------------
// out_slot[p, d] = sum_i a[p, i] * fc2[e, d, i]. Tile 128x128, BK=16, TM=TN=8.
__global__ __launch_bounds__(256) void k_fc2(const float* __restrict__ fc2w) {
    int e = blockIdx.z;
    int seg_beg = g_off[e];
    int seg_end = g_off[e + 1];
    int m0 = blockIdx.y * 128;
    int rows = seg_end - seg_beg - m0;
    if (rows <= 0) return;
    if (rows > 128) rows = 128;
    int n0 = blockIdx.x * 128;

    const float* W = fc2w + (size_t)e * D_MODEL * D_INT;

    __shared__ float As[16][132];
    __shared__ float Bs[16][128];
    __shared__ int   prs[128];

    int tid = threadIdx.x;
    if (tid < 128)
        prs[tid] = (tid < rows) ? g_pair[seg_beg + m0 + tid] : 0;
    __syncthreads();

    float acc[8][8];
#pragma unroll
    for (int i = 0; i < 8; i++)
#pragma unroll
        for (int j = 0; j < 8; j++) acc[i][j] = 0.f;

    int tx = tid & 15, ty = tid >> 4;
    int r8 = tid >> 1;          // row for both A and B loads (2 float4 each)
    int c8 = (tid & 1) * 8;

    const float* arow = g_a + (size_t)(seg_beg + m0 + r8) * D_INT + c8;
    const float* brow = W + (size_t)(n0 + r8) * D_INT + c8;

    for (int k0 = 0; k0 < D_INT; k0 += 16) {
        float4 a0, a1;
        if (r8 < rows) {
            a0 = *(const float4*)(arow + k0);
            a1 = *(const float4*)(arow + k0 + 4);
        } else {
            a0 = make_float4(0.f, 0.f, 0.f, 0.f);
            a1 = a0;
        }
        As[c8 + 0][r8] = a0.x; As[c8 + 1][r8] = a0.y;
        As[c8 + 2][r8] = a0.z; As[c8 + 3][r8] = a0.w;
        As[c8 + 4][r8] = a1.x; As[c8 + 5][r8] = a1.y;
        As[c8 + 6][r8] = a1.z; As[c8 + 7][r8] = a1.w;

        float4 b0 = *(const float4*)(brow + k0);
        float4 b1 = *(const float4*)(brow + k0 + 4);
        Bs[c8 + 0][r8] = b0.x; Bs[c8 + 1][r8] = b0.y;
        Bs[c8 + 2][r8] = b0.z; Bs[c8 + 3][r8] = b0.w;
        Bs[c8 + 4][r8] = b1.x; Bs[c8 + 5][r8] = b1.y;
        Bs[c8 + 6][r8] = b1.z; Bs[c8 + 7][r8] = b1.w;

        __syncthreads();

#pragma unroll
        for (int kk = 0; kk < 16; kk++) {
            float4 av0 = *(const float4*)&As[kk][ty * 8];
            float4 av1 = *(const float4*)&As[kk][ty * 8 + 4];
            float4 bv0 = *(const float4*)&Bs[kk][tx * 8];
            float4 bv1 = *(const float4*)&Bs[kk][tx * 8 + 4];
            float a[8] = {av0.x, av0.y, av0.z, av0.w, av1.x, av1.y, av1.z, av1.w};
            float b[8] = {bv0.x, bv0.y, bv0.z, bv0.w, bv1.x, bv1.y, bv1.z, bv1.w};
#pragma unroll
            for (int i = 0; i < 8; i++)
#pragma unroll
                for (int j = 0; j < 8; j++)
                    acc[i][j] += a[i] * b[j];
        }
        __syncthreads();
    }

#pragma unroll
    for (int i = 0; i < 8; i++) {
        int m = ty * 8 + i;
        if (m < rows) {
            float* op = g_slot + (size_t)prs[m] * D_MODEL + n0 + tx * 8;
            float4 r0 = {acc[i][0], acc[i][1], acc[i][2], acc[i][3]};
            float4 r1 = {acc[i][4], acc[i][5], acc[i][6], acc[i][7]};
            *(float4*)op       = r0;
            *(float4*)(op + 4) = r1;
        }
    }
}

// ---------------- combine ----------------
__global__ void k_combine(const float* __restrict__ wts, float* __restrict__ out) {
    int idx = blockIdx.x * blockDim.x + threadIdx.x;   // over N_TOK * (D_MODEL/4)
    if (idx >= N_TOK * (D_MODEL / 4)) return;
    int t = idx >> 8;         // D_MODEL/4 = 256
    int c = idx & 255;
    float w0 = wts[2 * t];
    float w1 = wts[2 * t + 1];
    float4 s0 = ((const float4*)(g_slot + (size_t)(2 * t) * D_MODEL))[c];
    float4 s1 = ((const float4*)(g_slot + (size_t)(2 * t + 1) * D_MODEL))[c];
    float4 r;
    r.x = w0 * s0.x + w1 * s1.x;
    r.y = w0 * s0.y + w1 * s1.y;
    r.z = w0 * s0.z + w1 * s1.z;
    r.w = w0 * s0.w + w1 * s1.w;
    ((float4*)out)[idx] = r;
}

extern "C" void kernel_launch(void* const* d_in, const int* in_sizes, int n_in,
                              void* d_out, int out_size) {
    const float* x      = (const float*)d_in[0];
    const float* wts    = (const float*)d_in[1];
    const int*   idx    = (const int*)d_in[2];
    const int*   counts = (const int*)d_in[3];
    const float* fc1w   = (const float*)d_in[4];
    const float* fc2w   = (const float*)d_in[5];
    float* out = (float*)d_out;

    k_offsets<<<1, 1>>>(counts);
    k_scatter<<<NPAIR / 256, 256>>>(idx);

    dim3 g1(D_INT / 64, (NPAIR + 127) / 128, NE);     // 8 x 32 x 8
    k_fc1<<<g1, 256>>>(x, fc1w);

    dim3 g2(D_MODEL / 128, (NPAIR + 127) / 128, NE);  // 8 x 32 x 8
    k_fc2<<<g2, 256>>>(fc2w);

    k_combine<<<(N_TOK * (D_MODEL / 4)) / 256, 256>>>(wts, out);
}

// round 3
// speedup vs baseline: 2.0353x; 2.0353x over previous
#include <cuda_runtime.h>
#include <cuda_bf16.h>
#include <cstdint>

#define N_TOK   2048
#define D_MODEL 1024
#define D_INT   512
#define NE      8
#define NPAIR   (N_TOK * 2)

#define BM 128
#define BN 128
#define BK 32
#define STAGES 3
#define TILE_BYTES 8192                    // 128 rows x 64B
#define STAGE_BYTES (4 * TILE_BYTES)       // Ah, Al, Bh, Bl
#define SMEM_SZ (STAGES * STAGE_BYTES)     // 96 KB

// ---- scratch (allocation-free: __device__ globals) ----
__device__ int   g_off[NE + 1];
__device__ int   g_cur[NE];
__device__ int   g_pair[NPAIR];
__device__ __nv_bfloat16 g_xh[(size_t)NPAIR * D_MODEL];
__device__ __nv_bfloat16 g_xl[(size_t)NPAIR * D_MODEL];
__device__ __nv_bfloat16 g_w1h[(size_t)NE * 1024 * D_MODEL];   // interleaved y/z rows
__device__ __nv_bfloat16 g_w1l[(size_t)NE * 1024 * D_MODEL];
__device__ __nv_bfloat16 g_w2h[(size_t)NE * D_MODEL * D_INT];
__device__ __nv_bfloat16 g_w2l[(size_t)NE * D_MODEL * D_INT];
__device__ __nv_bfloat16 g_ah[(size_t)NPAIR * D_INT];
__device__ __nv_bfloat16 g_al[(size_t)NPAIR * D_INT];

// ================= asm helpers (all compute_80-era, safe on compute_103) ====
__device__ __forceinline__ uint32_t smem_u32(const void* p) {
    uint32_t a;
    asm("{ .reg .u64 t; cvta.to.shared.u64 t, %1; cvt.u32.u64 %0, t; }" : "=r"(a) : "l"(p));
    return a;
}
__device__ __forceinline__ void cpa16(uint32_t d, const void* s) {
    asm volatile("cp.async.cg.shared.global [%0], [%1], 16;" :: "r"(d), "l"(s) : "memory");
}
__device__ __forceinline__ void cpa_commit() {
    asm volatile("cp.async.commit_group;" ::: "memory");
}
template <int N>
__device__ __forceinline__ void cpa_wait() {
    asm volatile("cp.async.wait_group %0;" :: "n"(N) : "memory");
}
__device__ __forceinline__ void ldsm4(uint32_t* r, uint32_t a) {
    asm volatile("ldmatrix.sync.aligned.m8n8.x4.shared.b16 {%0,%1,%2,%3}, [%4];"
                 : "=r"(r[0]), "=r"(r[1]), "=r"(r[2]), "=r"(r[3]) : "r"(a));
}
__device__ __forceinline__ void mma_bf16(float* d, const uint32_t* a, const uint32_t* b) {
    asm volatile(
        "mma.sync.aligned.m16n8k16.row.col.f32.bf16.bf16.f32 "
        "{%0,%1,%2,%3}, {%4,%5,%6,%7}, {%8,%9}, {%0,%1,%2,%3};"
        : "+f"(d[0]), "+f"(d[1]), "+f"(d[2]), "+f"(d[3])
        : "r"(a[0]), "r"(a[1]), "r"(a[2]), "r"(a[3]), "r"(b[0]), "r"(b[1]));
}
// XOR swizzle: 64B rows, 16B chunks; conflict-free for both cp.async and ldmatrix
__device__ __forceinline__ uint32_t swz(int row, int chunk) {
    return (uint32_t)(row * 64 + ((chunk ^ ((row >> 1) & 3)) << 4));
}

// ================= setup =================
__global__ void k_offsets(const int* __restrict__ counts) {
    int o = 0;
    g_off[0] = 0;
    for (int e = 0; e < NE; e++) { o += counts[e]; g_off[e + 1] = o; g_cur[e] = g_off[e]; }
}
__global__ void k_scatter(const int* __restrict__ indices) {
    int p = blockIdx.x * blockDim.x + threadIdx.x;
    if (p >= NPAIR) return;
    int e = indices[p];
    int pos = atomicAdd(&g_cur[e], 1);
    g_pair[pos] = p;
}
__global__ void k_zero(float* __restrict__ out) {
    int i = blockIdx.x * blockDim.x + threadIdx.x;   // N_TOK*D_MODEL/4 total
    ((float4*)out)[i] = make_float4(0.f, 0.f, 0.f, 0.f);
}

// ================= conversions =================
__device__ __forceinline__ void split4(float4 v, __nv_bfloat16* h4, __nv_bfloat16* l4) {
    float f[4] = {v.x, v.y, v.z, v.w};
#pragma unroll
    for (int i = 0; i < 4; i++) {
        __nv_bfloat16 h = __float2bfloat16(f[i]);
        h4[i] = h;
        l4[i] = __float2bfloat16(f[i] - __bfloat162float(h));
    }
}
__global__ void k_conv_x(const float* __restrict__ x) {
    int gid = blockIdx.x * blockDim.x + threadIdx.x;   // NPAIR*256
    if (gid >= NPAIR * 256) return;
    int s = gid >> 8;
    int k4 = (gid & 255) << 2;
    int t = g_pair[s] >> 1;
    float4 v = *(const float4*)(x + (size_t)t * D_MODEL + k4);
    __nv_bfloat16 h[4], l[4];
    split4(v, h, l);
    *(uint2*)(g_xh + (size_t)s * D_MODEL + k4) = *(uint2*)h;
    *(uint2*)(g_xl + (size_t)s * D_MODEL + k4) = *(uint2*)l;
}
__global__ void k_conv_w1(const float* __restrict__ w) {
    int gid = blockIdx.x * blockDim.x + threadIdx.x;   // NE*1024*256
    if (gid >= NE * 1024 * 256) return;
    int e = gid >> 18;
    int rem = gid & 262143;
    int r = rem >> 8;                 // interleaved out row: j=r>>1, gate=r&1
    int k4 = (rem & 255) << 2;
    int j = r >> 1, g = r & 1;
    float4 v = *(const float4*)(w + (size_t)e * (2 * D_INT * D_MODEL)
                                  + (size_t)(g * D_INT + j) * D_MODEL + k4);
    __nv_bfloat16 h[4], l[4];
    split4(v, h, l);
    size_t o = ((size_t)e * 1024 + r) * D_MODEL + k4;
    *(uint2*)(g_w1h + o) = *(uint2*)h;
    *(uint2*)(g_w1l + o) = *(uint2*)l;
}
__global__ void k_conv_w2(const float* __restrict__ w) {
    int gid = blockIdx.x * blockDim.x + threadIdx.x;   // NE*1024*128
    if (gid >= NE * 1024 * 128) return;
    int e = gid >> 17;
    int rem = gid & 131071;
    int r = rem >> 7;
    int k4 = (rem & 127) << 2;
    float4 v = *(const float4*)(w + (size_t)e * (D_MODEL * D_INT) + (size_t)r * D_INT + k4);
    __nv_bfloat16 h[4], l[4];
    split4(v, h, l);
    size_t o = ((size_t)e * 1024 + r) * D_INT + k4;
    *(uint2*)(g_w2h + o) = *(uint2*)h;
    *(uint2*)(g_w2l + o) = *(uint2*)l;
}

// ================= grouped split-bf16 MMA GEMM =================
// C[m,n] = sum_k A[m,k]*B[n,k] with A,B given as (hi,lo) bf16 pairs;
// 3-term: AhBh + AhBl + AlBh into fp32 accumulators.
// FC1: A=g_xh/g_xl (K=1024), B=g_w1h/g_w1l rows e*1024+n (y/z interleaved).
//      Epilogue: a = y*silu(z), split -> g_ah/g_al.
// FC2: A=g_ah/g_al (K=512),  B=g_w2h/g_w2l. Epilogue: atomicAdd w*val into out.
template<int K, bool FC1>
__global__ __launch_bounds__(256, 1) void k_mma(
    const __nv_bfloat16* __restrict__ Ah, const __nv_bfloat16* __restrict__ Al,
    const __nv_bfloat16* __restrict__ Bh, const __nv_bfloat16* __restrict__ Bl,
    const float* __restrict__ wts, float* __restrict__ out)
{
    const int KT = K / BK;

    int e = blockIdx.z;
    int seg_beg = g_off[e];
    int seg_end = g_off[e + 1];
    int m0 = blockIdx.y * BM;
    int rows = seg_end - seg_beg - m0;
    if (rows <= 0) return;
    if (rows > BM) rows = BM;
    int n0 = blockIdx.x * BN;
    int arow0 = seg_beg + m0;
    int brow0 = e * 1024 + n0;

    extern __shared__ __align__(128) char smem[];
    uint32_t sb = smem_u32(smem);

    int tid = threadIdx.x;
    int lane = tid & 31;
    int wid = tid >> 5;

    // ---- load indexing: thread covers rows (tid>>2) and (tid>>2)+64, chunk tid&3
    int lrow = tid >> 2;
    int lchk = tid & 3;
    uint32_t d0 = swz(lrow, lchk);
    uint32_t d1 = swz(lrow + 64, lchk);
    int gra0 = arow0 + lrow;        if (gra0 > NPAIR - 1) gra0 = NPAIR - 1;
    int gra1 = arow0 + lrow + 64;   if (gra1 > NPAIR - 1) gra1 = NPAIR - 1;
    int grb0 = brow0 + lrow;
    int grb1 = brow0 + lrow + 64;

    auto load_stage = [&](int s, int kt) {
        uint32_t base = sb + s * STAGE_BYTES;
        int ke = kt * BK + lchk * 8;
        cpa16(base + d0,                   Ah + (size_t)gra0 * K + ke);
        cpa16(base + d1,                   Ah + (size_t)gra1 * K + ke);
        cpa16(base + TILE_BYTES + d0,      Al + (size_t)gra0 * K + ke);
        cpa16(base + TILE_BYTES + d1,      Al + (size_t)gra1 * K + ke);
        cpa16(base + 2 * TILE_BYTES + d0,  Bh + (size_t)grb0 * K + ke);
        cpa16(base + 2 * TILE_BYTES + d1,  Bh + (size_t)grb1 * K + ke);
        cpa16(base + 3 * TILE_BYTES + d0,  Bl + (size_t)grb0 * K + ke);
        cpa16(base + 3 * TILE_BYTES + d1,  Bl + (size_t)grb1 * K + ke);
    };

    // ---- warp tiling: 2 (m) x 4 (n); warp tile 64m x 32n
    int wm = wid & 1, wn = wid >> 1;
    int m_off = wm * 64, n_off = wn * 32;

    float acc[4][4][4];
#pragma unroll
    for (int i = 0; i < 4; i++)
#pragma unroll
        for (int j = 0; j < 4; j++)
#pragma unroll
            for (int q = 0; q < 4; q++) acc[i][j][q] = 0.f;

    // prologue
    load_stage(0, 0); cpa_commit();
    load_stage(1, 1); cpa_commit();

    int arow_l = m_off + (lane & 15);
    int akoff  = lane >> 4;
    int brow_l = n_off + (lane & 7) + ((lane >> 4) << 3);
    int bkoff  = (lane >> 3) & 1;

    for (int kt = 0; kt < KT; kt++) {
        cpa_wait<STAGES - 2>();
        __syncthreads();
        if (kt + STAGES - 1 < KT) load_stage((kt + STAGES - 1) % STAGES, kt + STAGES - 1);
        cpa_commit();

        uint32_t base = sb + (kt % STAGES) * STAGE_BYTES;
#pragma unroll
        for (int ks = 0; ks < 2; ks++) {
            uint32_t ahf[4][4], alf[4][4], bhf[2][4], blf[2][4];
            int ak = ks * 2 + akoff;
#pragma unroll
            for (int mf = 0; mf < 4; mf++) {
                uint32_t ad = base + swz(arow_l + mf * 16, ak);
                ldsm4(ahf[mf], ad);
                ldsm4(alf[mf], ad + TILE_BYTES);
            }
            int bk = ks * 2 + bkoff;
#pragma unroll
            for (int ng = 0; ng < 2; ng++) {
                uint32_t bd = base + 2 * TILE_BYTES + swz(brow_l + ng * 16, bk);
                ldsm4(bhf[ng], bd);
                ldsm4(blf[ng], bd + TILE_BYTES);
            }
            // pass 1: Ah*Bh
#pragma unroll
            for (int mf = 0; mf < 4; mf++)
#pragma unroll
                for (int nt = 0; nt < 4; nt++)
                    mma_bf16(acc[mf][nt], ahf[mf], &bhf[nt >> 1][(nt & 1) * 2]);
            // pass 2: Ah*Bl
#pragma unroll
            for (int mf = 0; mf < 4; mf++)
#pragma unroll
                for (int nt = 0; nt < 4; nt++)
                    mma_bf16(acc[mf][nt], ahf[mf], &blf[nt >> 1][(nt & 1) * 2]);
            // pass 3: Al*Bh
#pragma unroll
            for (int mf = 0; mf < 4; mf++)
#pragma unroll
                for (int nt = 0; nt < 4; nt++)
                    mma_bf16(acc[mf][nt], alf[mf], &bhf[nt >> 1][(nt & 1) * 2]);
        }
    }

    // ---- epilogue ----
    int rq = lane >> 2;          // row within 16-frag
    int cq = lane & 3;           // col quad
#pragma unroll
    for (int mf = 0; mf < 4; mf++) {
#pragma unroll
        for (int half = 0; half < 2; half++) {
            int mloc = m_off + mf * 16 + rq + half * 8;
            bool act = (mloc < rows);
            if (FC1) {
#pragma unroll
                for (int nt = 0; nt < 4; nt++) {
                    float y = acc[mf][nt][half * 2];
                    float z = acc[mf][nt][half * 2 + 1];
                    float a = y * z * (1.f / (1.f + __expf(-z)));
                    __nv_bfloat16 h = __float2bfloat16(a);
                    __nv_bfloat16 l = __float2bfloat16(a - __bfloat162float(h));
                    if (act) {
                        int j = ((n0 + n_off + nt * 8) >> 1) + cq;
                        size_t o = (size_t)(arow0 + mloc) * D_INT + j;
                        g_ah[o] = h;
                        g_al[o] = l;
                    }
                }
            } else {
                if (act) {
                    int p = g_pair[arow0 + mloc];
                    int t = p >> 1;
                    float w = wts[p];
                    float* ob = out + (size_t)t * D_MODEL;
#pragma unroll
                    for (int nt = 0; nt < 4; nt++) {
                        int nc = n0 + n_off + nt * 8 + cq * 2;
                        atomicAdd(ob + nc,     w * acc[mf][nt][half * 2]);
                        atomicAdd(ob + nc + 1, w * acc[mf][nt][half * 2 + 1]);
                    }
                }
            }
        }
    }
}

// ================= host =================
extern "C" void kernel_launch(void* const* d_in, const int* in_sizes, int n_in,
                              void* d_out, int out_size) {
    const float* x      = (const float*)d_in[0];
    const float* wts    = (const float*)d_in[1];
    const int*   idx    = (const int*)d_in[2];
    const int*   counts = (const int*)d_in[3];
    const float* fc1w   = (const float*)d_in[4];
    const float* fc2w   = (const float*)d_in[5];
    float* out = (float*)d_out;

    static bool attr_done = false;
    if (!attr_done) {
        cudaFuncSetAttribute(k_mma<D_MODEL, true>,
                             cudaFuncAttributeMaxDynamicSharedMemorySize, SMEM_SZ);
        cudaFuncSetAttribute(k_mma<D_INT, false>,
                             cudaFuncAttributeMaxDynamicSharedMemorySize, SMEM_SZ);
        attr_done = true;
    }

    void *p_xh, *p_xl, *p_w1h, *p_w1l, *p_w2h, *p_w2l, *p_ah, *p_al;
    cudaGetSymbolAddress(&p_xh, g_xh);   cudaGetSymbolAddress(&p_xl, g_xl);
    cudaGetSymbolAddress(&p_w1h, g_w1h); cudaGetSymbolAddress(&p_w1l, g_w1l);
    cudaGetSymbolAddress(&p_w2h, g_w2h); cudaGetSymbolAddress(&p_w2l, g_w2l);
    cudaGetSymbolAddress(&p_ah, g_ah);   cudaGetSymbolAddress(&p_al, g_al);

    k_offsets<<<1, 1>>>(counts);
    k_scatter<<<NPAIR / 256, 256>>>(idx);
    k_conv_x<<<(NPAIR * 256) / 256, 256>>>(x);
    k_conv_w1<<<(NE * 1024 * 256) / 256, 256>>>(fc1w);
    k_conv_w2<<<(NE * 1024 * 128) / 256, 256>>>(fc2w);
    k_zero<<<(N_TOK * D_MODEL / 4) / 256, 256>>>(out);

    dim3 g1(1024 / BN, NPAIR / BM, NE);   // interleaved fc1 out dim = 1024
    k_mma<D_MODEL, true><<<g1, 256, SMEM_SZ>>>(
        (const __nv_bfloat16*)p_xh, (const __nv_bfloat16*)p_xl,
        (const __nv_bfloat16*)p_w1h, (const __nv_bfloat16*)p_w1l, wts, out);

    dim3 g2(D_MODEL / BN, NPAIR / BM, NE);
    k_mma<D_INT, false><<<g2, 256, SMEM_SZ>>>(
        (const __nv_bfloat16*)p_ah, (const __nv_bfloat16*)p_al,
        (const __nv_bfloat16*)p_w2h, (const __nv_bfloat16*)p_w2l, wts, out);
}

// round 4
// speedup vs baseline: 3.0761x; 1.5114x over previous
#include <cuda_runtime.h>
#include <cuda_fp16.h>
#include <cstdint>

#define N_TOK   2048
#define D_MODEL 1024
#define D_INT   512
#define NE      8
#define NPAIR   (N_TOK * 2)
#define NPAD    5120              // segments padded to 128-row tiles (40 tiles)
#define KT1     32                // k-tiles fc1 (K=1024, BK=32)
#define KT2     16                // k-tiles fc2 (K=512)

#define TILE_BYTES  16384         // one A-pair tile (Ah8K+Al8K) or one B tile (256x32 fp16)
#define STAGE_BYTES 32768         // A pair + B
#define NSTAGE      4
#define SMEM_SZ     (1024 + NSTAGE * STAGE_BYTES)   // 132 KB

// ---- scratch (allocation-free: __device__ globals) ----
__device__ int g_poff[NE + 1];
__device__ int g_cnt[NE];
__device__ int g_cur[NE];
__device__ int g_pair[NPAD];
__device__ __align__(16) char g_A1[(size_t)(NPAD / 128) * KT1 * TILE_BYTES]; // 20MB
__device__ __align__(16) char g_B1[(size_t)NE * 4 * KT1 * TILE_BYTES];       // 16MB
__device__ __align__(16) char g_A2[(size_t)(NPAD / 128) * KT2 * TILE_BYTES]; // 10MB
__device__ __align__(16) char g_B2[(size_t)NE * 4 * KT2 * TILE_BYTES];       // 8MB

// ================= asm helpers (sm_90-base PTX only; no 'a' features) ======
__device__ __forceinline__ uint32_t smem_u32(const void* p) {
    uint32_t a;
    asm("{ .reg .u64 t; cvta.to.shared.u64 t, %1; cvt.u32.u64 %0, t; }" : "=r"(a) : "l"(p));
    return a;
}
__device__ __forceinline__ void mbar_init(uint32_t a, uint32_t cnt) {
    asm volatile("mbarrier.init.shared::cta.b64 [%0], %1;" :: "r"(a), "r"(cnt) : "memory");
}
__device__ __forceinline__ void mbar_expect_tx(uint32_t a, uint32_t bytes) {
    asm volatile("mbarrier.arrive.expect_tx.shared::cta.b64 _, [%0], %1;"
                 :: "r"(a), "r"(bytes) : "memory");
}
__device__ __forceinline__ void mwait(uint32_t a, uint32_t ph) {
    asm volatile(
        "{\n\t.reg .pred P;\n"
        "W%=:\n\t"
        "mbarrier.try_wait.parity.acquire.cta.shared::cta.b64 P, [%0], %1, 0x989680;\n\t"
        "@P bra D%=;\n\t"
        "bra W%=;\n"
        "D%=:\n\t}"
        :: "r"(a), "r"(ph) : "memory");
}
__device__ __forceinline__ void bulk_g2s(uint32_t dst, const void* src, uint32_t bytes, uint32_t mbar) {
    asm volatile(
        "cp.async.bulk.shared::cluster.global.mbarrier::complete_tx::bytes [%0], [%1], %2, [%3];"
        :: "r"(dst), "l"(src), "r"(bytes), "r"(mbar) : "memory");
}
__device__ __forceinline__ void ldsm4(uint32_t* r, uint32_t a) {
    asm volatile("ldmatrix.sync.aligned.m8n8.x4.shared.b16 {%0,%1,%2,%3}, [%4];"
                 : "=r"(r[0]), "=r"(r[1]), "=r"(r[2]), "=r"(r[3]) : "r"(a));
}
__device__ __forceinline__ void mma_f16(float* d, const uint32_t* a, const uint32_t* b) {
    asm volatile(
        "mma.sync.aligned.m16n8k16.row.col.f32.f16.f16.f32 "
        "{%0,%1,%2,%3}, {%4,%5,%6,%7}, {%8,%9}, {%0,%1,%2,%3};"
        : "+f"(d[0]), "+f"(d[1]), "+f"(d[2]), "+f"(d[3])
        : "r"(a[0]), "r"(a[1]), "r"(a[2]), "r"(a[3]), "r"(b[0]), "r"(b[1]));
}
// XOR swizzle within a tile: 64B per row, 16B chunks
__device__ __forceinline__ uint32_t swz(int row, int chunk) {
    return (uint32_t)(row * 64 + ((chunk ^ ((row >> 1) & 3)) << 4));
}

// ================= setup =================
__global__ void k_painit() {
    g_pair[blockIdx.x * 256 + threadIdx.x] = -1;
}
__global__ void k_offsets(const int* __restrict__ counts) {
    int o = 0;
    g_poff[0] = 0;
    for (int e = 0; e < NE; e++) {
        int c = counts[e];
        g_cnt[e] = c;
        g_cur[e] = o;
        o += ((c + 127) >> 7) << 7;
        g_poff[e + 1] = o;
    }
}
__global__ void k_scatter(const int* __restrict__ indices) {
    int p = blockIdx.x * blockDim.x + threadIdx.x;
    if (p >= NPAIR) return;
    int e = indices[p];
    int pos = atomicAdd(&g_cur[e], 1);
    g_pair[pos] = p;
}
__global__ void k_zero(float* __restrict__ out) {
    int i = blockIdx.x * blockDim.x + threadIdx.x;
    ((float4*)out)[i] = make_float4(0.f, 0.f, 0.f, 0.f);
}

// ================= conversions into tiled, pre-swizzled fp16 ===============
__device__ __forceinline__ void pack8(const float* f, uint4& hi, uint4& lo) {
    __half h[8], l[8];
#pragma unroll
    for (int i = 0; i < 8; i++) {
        h[i] = __float2half_rn(f[i]);
        l[i] = __float2half_rn(f[i] - __half2float(h[i]));
    }
    hi = *(uint4*)h;
    lo = *(uint4*)l;
}

// x -> g_A1: tile = ((s>>7)*KT1 + k/32), within: swz(s&127, (k&31)/8), hi at +0, lo at +8192
__global__ void k_conv_x(const float* __restrict__ x) {
    int gid = blockIdx.x * 256 + threadIdx.x;   // NPAD * 128
    int s = gid >> 7;
    int k8 = gid & 127;
    char* dst = g_A1 + (size_t)((s >> 7) * KT1 + (k8 >> 2)) * TILE_BYTES + swz(s & 127, k8 & 3);
    int pr = g_pair[s];
    if (pr < 0) {
        uint4 z = make_uint4(0, 0, 0, 0);
        *(uint4*)dst = z;
        *(uint4*)(dst + 8192) = z;
        return;
    }
    const float* sp = x + (size_t)(pr >> 1) * D_MODEL + k8 * 8;
    float f[8];
    *(float4*)&f[0] = *(const float4*)sp;
    *(float4*)&f[4] = *(const float4*)(sp + 4);
    uint4 hi, lo;
    pack8(f, hi, lo);
    *(uint4*)dst = hi;
    *(uint4*)(dst + 8192) = lo;
}

// fc1 weights -> g_B1, rows interleaved (y,z): row n = 2*j + gate
__global__ void k_conv_w1(const float* __restrict__ w) {
    int gid = blockIdx.x * 256 + threadIdx.x;   // NE*1024*128
    int e = gid >> 17;
    int rem = gid & 131071;
    int n = rem >> 7;
    int k8 = rem & 127;
    int j = n >> 1, g = n & 1;
    const float* sp = w + (size_t)e * (2 * D_INT * D_MODEL) + (size_t)(g * D_INT + j) * D_MODEL + k8 * 8;
    float f[8];
    *(float4*)&f[0] = *(const float4*)sp;
    *(float4*)&f[4] = *(const float4*)(sp + 4);
    __half h[8];
#pragma unroll
    for (int i = 0; i < 8; i++) h[i] = __float2half_rn(f[i]);
    char* dst = g_B1 + (size_t)((e * 4 + (n >> 8)) * KT1 + (k8 >> 2)) * TILE_BYTES + swz(n & 255, k8 & 3);
    *(uint4*)dst = *(uint4*)h;
}

// fc2 weights -> g_B2
__global__ void k_conv_w2(const float* __restrict__ w) {
    int gid = blockIdx.x * 256 + threadIdx.x;   // NE*1024*64
    int e = gid >> 16;
    int rem = gid & 65535;
    int n = rem >> 6;
    int k8 = rem & 63;
    const float* sp = w + (size_t)e * (D_MODEL * D_INT) + (size_t)n * D_INT + k8 * 8;
    float f[8];
    *(float4*)&f[0] = *(const float4*)sp;
    *(float4*)&f[4] = *(const float4*)(sp + 4);
    __half h[8];
#pragma unroll
    for (int i = 0; i < 8; i++) h[i] = __float2half_rn(f[i]);
    char* dst = g_B2 + (size_t)((e * 4 + (n >> 8)) * KT2 + (k8 >> 2)) * TILE_BYTES + swz(n & 255, k8 & 3);
    *(uint4*)dst = *(uint4*)h;
}

// ================= grouped split-fp16 MMA GEMM (bulk-copy pipeline) ========
// 2-term: (Ah + Al) * B, A split fp16 (exact), B single fp16.
// Tiles: BM=128, BN=256, BK=32; 8 warps, warp tile 64x64.
// FC1 epilogue: a=y*silu(z), split fp16 -> g_A2 (tiled). FC2: atomicAdd into out.
template<int KT, bool FC1>
__global__ __launch_bounds__(256, 1) void k_mma(
    const char* __restrict__ Abuf, const char* __restrict__ Bbuf,
    const float* __restrict__ wts, float* __restrict__ out)
{
    int e = blockIdx.z;
    int cnt = g_cnt[e];
    int mbl = blockIdx.y;
    int rows = cnt - mbl * 128;
    if (rows <= 0) return;
    if (rows > 128) rows = 128;
    int nb = blockIdx.x;
    int arow0 = g_poff[e] + mbl * 128;
    size_t atile = (size_t)((arow0 >> 7) * KT);
    size_t btile = (size_t)((e * 4 + nb) * KT);
    const int n0 = nb * 256;

    extern __shared__ __align__(128) char smem[];
    uint32_t sb = smem_u32(smem);
    int tid = threadIdx.x, lane = tid & 31, wid = tid >> 5;

    if (tid < NSTAGE) mbar_init(sb + tid * 8, 1);
    __syncthreads();
    if (tid == 0) {
        asm volatile("fence.proxy.async.shared::cta;" ::: "memory");
#pragma unroll
        for (int s = 0; s < NSTAGE; s++) {
            mbar_expect_tx(sb + s * 8, STAGE_BYTES);
            uint32_t d = sb + 1024 + s * STAGE_BYTES;
            bulk_g2s(d,              Abuf + (atile + s) * TILE_BYTES, TILE_BYTES, sb + s * 8);
            bulk_g2s(d + TILE_BYTES, Bbuf + (btile + s) * TILE_BYTES, TILE_BYTES, sb + s * 8);
        }
    }

    int wm = wid & 1, wn = wid >> 1;
    int m_off = wm * 64, n_off = wn * 64;

    float acc[4][8][4];
#pragma unroll
    for (int i = 0; i < 4; i++)
#pragma unroll
        for (int j = 0; j < 8; j++)
#pragma unroll
            for (int q = 0; q < 4; q++) acc[i][j][q] = 0.f;

    int arow_l = m_off + (lane & 15);
    int akoff  = lane >> 4;
    int brow_l = n_off + (lane & 7) + ((lane >> 4) << 3);
    int bkoff  = (lane >> 3) & 1;

    for (int kt = 0; kt < KT; kt++) {
        int slot = kt & (NSTAGE - 1);
        mwait(sb + slot * 8, (kt >> 2) & 1);
        uint32_t base = sb + 1024 + slot * STAGE_BYTES;

#pragma unroll
        for (int ks = 0; ks < 2; ks++) {
            uint32_t ahf[4][4], alf[4][4];
            int ak = ks * 2 + akoff;
#pragma unroll
            for (int mf = 0; mf < 4; mf++) {
                uint32_t ad = base + swz(arow_l + mf * 16, ak);
                ldsm4(ahf[mf], ad);
                ldsm4(alf[mf], ad + 8192);
            }
            int bk = ks * 2 + bkoff;
#pragma unroll
            for (int ng = 0; ng < 4; ng++) {
                uint32_t bf[4];
                ldsm4(bf, base + TILE_BYTES + swz(brow_l + ng * 16, bk));
#pragma unroll
                for (int mf = 0; mf < 4; mf++) {
                    mma_f16(acc[mf][2 * ng],     ahf[mf], &bf[0]);
                    mma_f16(acc[mf][2 * ng + 1], ahf[mf], &bf[2]);
                }
#pragma unroll
                for (int mf = 0; mf < 4; mf++) {
                    mma_f16(acc[mf][2 * ng],     alf[mf], &bf[0]);
                    mma_f16(acc[mf][2 * ng + 1], alf[mf], &bf[2]);
                }
            }
        }
        __syncthreads();
        if (tid == 0 && kt + NSTAGE < KT) {
            mbar_expect_tx(sb + slot * 8, STAGE_BYTES);
            bulk_g2s(base,              Abuf + (atile + kt + NSTAGE) * TILE_BYTES, TILE_BYTES, sb + slot * 8);
            bulk_g2s(base + TILE_BYTES, Bbuf + (btile + kt + NSTAGE) * TILE_BYTES, TILE_BYTES, sb + slot * 8);
        }
    }

    // ---- epilogue ----
    int rq = lane >> 2, cq = lane & 3;
#pragma unroll
    for (int mf = 0; mf < 4; mf++) {
#pragma unroll
        for (int half = 0; half < 2; half++) {
            int mloc = m_off + mf * 16 + rq + half * 8;
            if (mloc >= rows) continue;
            int s = arow0 + mloc;
            if (FC1) {
                int r = s & 127;
                size_t trow = (size_t)(s >> 7) * KT2;
#pragma unroll
                for (int nt = 0; nt < 8; nt++) {
                    float y = acc[mf][nt][half * 2];
                    float z = acc[mf][nt][half * 2 + 1];
                    float a = y * z * (1.f / (1.f + __expf(-z)));
                    __half h = __float2half_rn(a);
                    __half l = __float2half_rn(a - __half2float(h));
                    int j = ((n0 + n_off + nt * 8) >> 1) + cq;
                    char* p = g_A2 + (trow + (j >> 5)) * TILE_BYTES + swz(r, (j & 31) >> 3) + (j & 7) * 2;
                    *(__half*)p = h;
                    *(__half*)(p + 8192) = l;
                }
            } else {
                int pr = g_pair[s];
                float w = wts[pr];
                float* ob = out + (size_t)(pr >> 1) * D_MODEL;
#pragma unroll
                for (int nt = 0; nt < 8; nt++) {
                    int nc = n0 + n_off + nt * 8 + cq * 2;
                    atomicAdd(ob + nc,     w * acc[mf][nt][half * 2]);
                    atomicAdd(ob + nc + 1, w * acc[mf][nt][half * 2 + 1]);
                }
            }
        }
    }
}

// ================= host =================
extern "C" void kernel_launch(void* const* d_in, const int* in_sizes, int n_in,
                              void* d_out, int out_size) {
    const float* x      = (const float*)d_in[0];
    const float* wts    = (const float*)d_in[1];
    const int*   idx    = (const int*)d_in[2];
    const int*   counts = (const int*)d_in[3];
    const float* fc1w   = (const float*)d_in[4];
    const float* fc2w   = (const float*)d_in[5];
    float* out = (float*)d_out;

    cudaFuncSetAttribute(k_mma<KT1, true>,
                         cudaFuncAttributeMaxDynamicSharedMemorySize, SMEM_SZ);
    cudaFuncSetAttribute(k_mma<KT2, false>,
                         cudaFuncAttributeMaxDynamicSharedMemorySize, SMEM_SZ);

    void *pA1, *pB1, *pA2, *pB2;
    cudaGetSymbolAddress(&pA1, g_A1);
    cudaGetSymbolAddress(&pB1, g_B1);
    cudaGetSymbolAddress(&pA2, g_A2);
    cudaGetSymbolAddress(&pB2, g_B2);

    k_painit<<<NPAD / 256, 256>>>();
    k_offsets<<<1, 1>>>(counts);
    k_scatter<<<NPAIR / 256, 256>>>(idx);
    k_conv_x<<<(NPAD * 128) / 256, 256>>>(x);
    k_conv_w1<<<(NE * 1024 * 128) / 256, 256>>>(fc1w);
    k_conv_w2<<<(NE * 1024 * 64) / 256, 256>>>(fc2w);
    k_zero<<<(N_TOK * D_MODEL / 4) / 256, 256>>>(out);

    dim3 g(4, 32, NE);
    k_mma<KT1, true><<<g, 256, SMEM_SZ>>>((const char*)pA1, (const char*)pB1, wts, out);
    k_mma<KT2, false><<<g, 256, SMEM_SZ>>>((const char*)pA2, (const char*)pB2, wts, out);
}

// round 5
// speedup vs baseline: 4.0788x; 1.3260x over previous
#include <cuda_runtime.h>
#include <cuda_fp16.h>
#include <cstdint>

#define N_TOK   2048
#define D_MODEL 1024
#define D_INT   512
#define NE      8
#define NPAIR   (N_TOK * 2)
#define NPAD    5120              // segments padded to 128-row tiles (40 tiles)
#define KT1     32                // k-tiles fc1 (K=1024, BK=32)
#define KT2     16                // k-tiles fc2 (K=512)

#define TILE_A      8192          // 128 rows x 64B (fp16, BK=32)
#define TILE_B      16384         // 256 rows x 64B
#define STAGE_BYTES (TILE_A + TILE_B)
#define NSTAGE      4
#define SMEM_SZ     (1024 + NSTAGE * STAGE_BYTES)   // ~97 KB

// ---- scratch (allocation-free: __device__ globals) ----
__device__ int g_poff[NE + 1];
__device__ int g_cnt[NE];
__device__ int g_cur[NE];
__device__ int g_pair[NPAD];
__device__ __align__(16) char g_A1[(size_t)(NPAD / 128) * KT1 * TILE_A];  // 10MB
__device__ __align__(16) char g_B1[(size_t)NE * 4 * KT1 * TILE_B];        // 16MB
__device__ __align__(16) char g_A2[(size_t)(NPAD / 128) * KT2 * TILE_A];  // 5MB
__device__ __align__(16) char g_B2[(size_t)NE * 4 * KT2 * TILE_B];        // 8MB

// ================= asm helpers (sm_90-base PTX only) =================
__device__ __forceinline__ uint32_t smem_u32(const void* p) {
    uint32_t a;
    asm("{ .reg .u64 t; cvta.to.shared.u64 t, %1; cvt.u32.u64 %0, t; }" : "=r"(a) : "l"(p));
    return a;
}
__device__ __forceinline__ void mbar_init(uint32_t a, uint32_t cnt) {
    asm volatile("mbarrier.init.shared::cta.b64 [%0], %1;" :: "r"(a), "r"(cnt) : "memory");
}
__device__ __forceinline__ void mbar_expect_tx(uint32_t a, uint32_t bytes) {
    asm volatile("mbarrier.arrive.expect_tx.shared::cta.b64 _, [%0], %1;"
                 :: "r"(a), "r"(bytes) : "memory");
}
__device__ __forceinline__ void mwait(uint32_t a, uint32_t ph) {
    asm volatile(
        "{\n\t.reg .pred P;\n"
        "W%=:\n\t"
        "mbarrier.try_wait.parity.acquire.cta.shared::cta.b64 P, [%0], %1, 0x989680;\n\t"
        "@P bra D%=;\n\t"
        "bra W%=;\n"
        "D%=:\n\t}"
        :: "r"(a), "r"(ph) : "memory");
}
__device__ __forceinline__ void bulk_g2s(uint32_t dst, const void* src, uint32_t bytes, uint32_t mbar) {
    asm volatile(
        "cp.async.bulk.shared::cluster.global.mbarrier::complete_tx::bytes [%0], [%1], %2, [%3];"
        :: "r"(dst), "l"(src), "r"(bytes), "r"(mbar) : "memory");
}
__device__ __forceinline__ void ldsm4(uint32_t* r, uint32_t a) {
    asm volatile("ldmatrix.sync.aligned.m8n8.x4.shared.b16 {%0,%1,%2,%3}, [%4];"
                 : "=r"(r[0]), "=r"(r[1]), "=r"(r[2]), "=r"(r[3]) : "r"(a));
}
__device__ __forceinline__ void mma_f16(float* d, const uint32_t* a, const uint32_t* b) {
    asm volatile(
        "mma.sync.aligned.m16n8k16.row.col.f32.f16.f16.f32 "
        "{%0,%1,%2,%3}, {%4,%5,%6,%7}, {%8,%9}, {%0,%1,%2,%3};"
        : "+f"(d[0]), "+f"(d[1]), "+f"(d[2]), "+f"(d[3])
        : "r"(a[0]), "r"(a[1]), "r"(a[2]), "r"(a[3]), "r"(b[0]), "r"(b[1]));
}
// XOR swizzle within a tile: 64B per row, 16B chunks
__device__ __forceinline__ uint32_t swz(int row, int chunk) {
    return (uint32_t)(row * 64 + ((chunk ^ ((row >> 1) & 3)) << 4));
}

// ================= setup =================
__global__ void k_painit() {
    g_pair[blockIdx.x * 256 + threadIdx.x] = -1;
}
__global__ void k_offsets(const int* __restrict__ counts) {
    int o = 0;
    g_poff[0] = 0;
    for (int e = 0; e < NE; e++) {
        int c = counts[e];
        g_cnt[e] = c;
        g_cur[e] = o;
        o += ((c + 127) >> 7) << 7;
        g_poff[e + 1] = o;
    }
}
__global__ void k_scatter(const int* __restrict__ indices) {
    int p = blockIdx.x * blockDim.x + threadIdx.x;
    if (p >= NPAIR) return;
    int e = indices[p];
    int pos = atomicAdd(&g_cur[e], 1);
    g_pair[pos] = p;
}
__global__ void k_zero(float* __restrict__ out) {
    int i = blockIdx.x * blockDim.x + threadIdx.x;
    ((float4*)out)[i] = make_float4(0.f, 0.f, 0.f, 0.f);
}

// ================= conversions into tiled, pre-swizzled fp16 ===============
// x -> g_A1: tile = (s>>7)*KT1 + k8>>2, within: swz(s&127, k8&3)
__global__ void k_conv_x(const float* __restrict__ x) {
    int gid = blockIdx.x * 256 + threadIdx.x;   // NPAD * 128
    int s = gid >> 7;
    int k8 = gid & 127;
    char* dst = g_A1 + (size_t)((s >> 7) * KT1 + (k8 >> 2)) * TILE_A + swz(s & 127, k8 & 3);
    int pr = g_pair[s];
    if (pr < 0) {
        *(uint4*)dst = make_uint4(0, 0, 0, 0);
        return;
    }
    const float* sp = x + (size_t)(pr >> 1) * D_MODEL + k8 * 8;
    float f[8];
    *(float4*)&f[0] = *(const float4*)sp;
    *(float4*)&f[4] = *(const float4*)(sp + 4);
    __half h[8];
#pragma unroll
    for (int i = 0; i < 8; i++) h[i] = __float2half_rn(f[i]);
    *(uint4*)dst = *(uint4*)h;
}

// fc1 weights -> g_B1, rows interleaved (y,z): row n = 2*j + gate
__global__ void k_conv_w1(const float* __restrict__ w) {
    int gid = blockIdx.x * 256 + threadIdx.x;   // NE*1024*128
    int e = gid >> 17;
    int rem = gid & 131071;
    int n = rem >> 7;
    int k8 = rem & 127;
    int j = n >> 1, g = n & 1;
    const float* sp = w + (size_t)e * (2 * D_INT * D_MODEL) + (size_t)(g * D_INT + j) * D_MODEL + k8 * 8;
    float f[8];
    *(float4*)&f[0] = *(const float4*)sp;
    *(float4*)&f[4] = *(const float4*)(sp + 4);
    __half h[8];
#pragma unroll
    for (int i = 0; i < 8; i++) h[i] = __float2half_rn(f[i]);
    char* dst = g_B1 + (size_t)((e * 4 + (n >> 8)) * KT1 + (k8 >> 2)) * TILE_B + swz(n & 255, k8 & 3);
    *(uint4*)dst = *(uint4*)h;
}

// fc2 weights -> g_B2
__global__ void k_conv_w2(const float* __restrict__ w) {
    int gid = blockIdx.x * 256 + threadIdx.x;   // NE*1024*64
    int e = gid >> 16;
    int rem = gid & 65535;
    int n = rem >> 6;
    int k8 = rem & 63;
    const float* sp = w + (size_t)e * (D_MODEL * D_INT) + (size_t)n * D_INT + k8 * 8;
    float f[8];
    *(float4*)&f[0] = *(const float4*)sp;
    *(float4*)&f[4] = *(const float4*)(sp + 4);
    __half h[8];
#pragma unroll
    for (int i = 0; i < 8; i++) h[i] = __float2half_rn(f[i]);
    char* dst = g_B2 + (size_t)((e * 4 + (n >> 8)) * KT2 + (k8 >> 2)) * TILE_B + swz(n & 255, k8 & 3);
    *(uint4*)dst = *(uint4*)h;
}

// ================= grouped fp16 MMA GEMM (bulk-copy pipeline) ========
// Single-term fp16: C = A*B, fp32 accumulate.
// Tiles: BM=128, BN=256, BK=32; 8 warps, warp tile 64x64.
// FC1 epilogue: a=y*silu(z) -> g_A2 (tiled fp16). FC2: atomicAdd w*val into out.
template<int KT, bool FC1>
__global__ __launch_bounds__(256, 1) void k_mma(
    const char* __restrict__ Abuf, const char* __restrict__ Bbuf,
    const float* __restrict__ wts, float* __restrict__ out)
{
    int e = blockIdx.z;
    int cnt = g_cnt[e];
    int mbl = blockIdx.y;
    int rows = cnt - mbl * 128;
    if (rows <= 0) return;
    if (rows > 128) rows = 128;
    int nb = blockIdx.x;
    int arow0 = g_poff[e] + mbl * 128;
    size_t atile = (size_t)((arow0 >> 7) * KT);
    size_t btile = (size_t)((e * 4 + nb) * KT);
    const int n0 = nb * 256;

    extern __shared__ __align__(128) char smem[];
    uint32_t sb = smem_u32(smem);
    int tid = threadIdx.x, lane = tid & 31, wid = tid >> 5;

    if (tid < NSTAGE) mbar_init(sb + tid * 8, 1);
    __syncthreads();
    if (tid == 0) {
        asm volatile("fence.proxy.async.shared::cta;" ::: "memory");
#pragma unroll
        for (int s = 0; s < NSTAGE; s++) {
            mbar_expect_tx(sb + s * 8, STAGE_BYTES);
            uint32_t d = sb + 1024 + s * STAGE_BYTES;
            bulk_g2s(d,          Abuf + (atile + s) * TILE_A, TILE_A, sb + s * 8);
            bulk_g2s(d + TILE_A, Bbuf + (btile + s) * TILE_B, TILE_B, sb + s * 8);
        }
    }

    int wm = wid & 1, wn = wid >> 1;
    int m_off = wm * 64, n_off = wn * 64;

    float acc[4][8][4];
#pragma unroll
    for (int i = 0; i < 4; i++)
#pragma unroll
        for (int j = 0; j < 8; j++)
#pragma unroll
            for (int q = 0; q < 4; q++) acc[i][j][q] = 0.f;

    int arow_l = m_off + (lane & 15);
    int akoff  = lane >> 4;
    int brow_l = n_off + (lane & 7) + ((lane >> 4) << 3);
    int bkoff  = (lane >> 3) & 1;

    for (int kt = 0; kt < KT; kt++) {
        int slot = kt & (NSTAGE - 1);
        mwait(sb + slot * 8, (kt >> 2) & 1);
        uint32_t base = sb + 1024 + slot * STAGE_BYTES;

#pragma unroll
        for (int ks = 0; ks < 2; ks++) {
            uint32_t ahf[4][4];
            int ak = ks * 2 + akoff;
#pragma unroll
            for (int mf = 0; mf < 4; mf++)
                ldsm4(ahf[mf], base + swz(arow_l + mf * 16, ak));
            int bk = ks * 2 + bkoff;
#pragma unroll
            for (int ng = 0; ng < 4; ng++) {
                uint32_t bf[4];
                ldsm4(bf, base + TILE_A + swz(brow_l + ng * 16, bk));
#pragma unroll
                for (int mf = 0; mf < 4; mf++) {
                    mma_f16(acc[mf][2 * ng],     ahf[mf], &bf[0]);
                    mma_f16(acc[mf][2 * ng + 1], ahf[mf], &bf[2]);
                }
            }
        }
        __syncthreads();
        if (tid == 0 && kt + NSTAGE < KT) {
            mbar_expect_tx(sb + slot * 8, STAGE_BYTES);
            bulk_g2s(base,          Abuf + (atile + kt + NSTAGE) * TILE_A, TILE_A, sb + slot * 8);
            bulk_g2s(base + TILE_A, Bbuf + (btile + kt + NSTAGE) * TILE_B, TILE_B, sb + slot * 8);
        }
    }

    // ---- epilogue ----
    int rq = lane >> 2, cq = lane & 3;
#pragma unroll
    for (int mf = 0; mf < 4; mf++) {
#pragma unroll
        for (int half = 0; half < 2; half++) {
            int mloc = m_off + mf * 16 + rq + half * 8;
            if (mloc >= rows) continue;
            int s = arow0 + mloc;
            if (FC1) {
                int r = s & 127;
                size_t trow = (size_t)(s >> 7) * KT2;
#pragma unroll
                for (int nt = 0; nt < 8; nt++) {
                    float y = acc[mf][nt][half * 2];
                    float z = acc[mf][nt][half * 2 + 1];
                    float a = y * z * (1.f / (1.f + __expf(-z)));
                    int j = ((n0 + n_off + nt * 8) >> 1) + cq;
                    char* p = g_A2 + (trow + (j >> 5)) * TILE_A + swz(r, (j & 31) >> 3) + (j & 7) * 2;
                    *(__half*)p = __float2half_rn(a);
                }
            } else {
                int pr = g_pair[s];
                float w = wts[pr];
                float* ob = out + (size_t)(pr >> 1) * D_MODEL;
#pragma unroll
                for (int nt = 0; nt < 8; nt++) {
                    int nc = n0 + n_off + nt * 8 + cq * 2;
                    atomicAdd(ob + nc,     w * acc[mf][nt][half * 2]);
                    atomicAdd(ob + nc + 1, w * acc[mf][nt][half * 2 + 1]);
                }
            }
        }
    }
}

// ================= host =================
extern "C" void kernel_launch(void* const* d_in, const int* in_sizes, int n_in,
                              void* d_out, int out_size) {
    const float* x      = (const float*)d_in[0];
    const float* wts    = (const float*)d_in[1];
    const int*   idx    = (const int*)d_in[2];
    const int*   counts = (const int*)d_in[3];
    const float* fc1w   = (const float*)d_in[4];
    const float* fc2w   = (const float*)d_in[5];
    float* out = (float*)d_out;

    cudaFuncSetAttribute(k_mma<KT1, true>,
                         cudaFuncAttributeMaxDynamicSharedMemorySize, SMEM_SZ);
    cudaFuncSetAttribute(k_mma<KT2, false>,
                         cudaFuncAttributeMaxDynamicSharedMemorySize, SMEM_SZ);

    void *pA1, *pB1, *pA2, *pB2;
    cudaGetSymbolAddress(&pA1, g_A1);
    cudaGetSymbolAddress(&pB1, g_B1);
    cudaGetSymbolAddress(&pA2, g_A2);
    cudaGetSymbolAddress(&pB2, g_B2);

    k_painit<<<NPAD / 256, 256>>>();
    k_offsets<<<1, 1>>>(counts);
    k_scatter<<<NPAIR / 256, 256>>>(idx);
    k_conv_x<<<(NPAD * 128) / 256, 256>>>(x);
    k_conv_w1<<<(NE * 1024 * 128) / 256, 256>>>(fc1w);
    k_conv_w2<<<(NE * 1024 * 64) / 256, 256>>>(fc2w);
    k_zero<<<(N_TOK * D_MODEL / 4) / 256, 256>>>(out);

    dim3 g(4, 32, NE);
    k_mma<KT1, true><<<g, 256, SMEM_SZ>>>((const char*)pA1, (const char*)pB1, wts, out);
    k_mma<KT2, false><<<g, 256, SMEM_SZ>>>((const char*)pA2, (const char*)pB2, wts, out);
}

// round 6
// speedup vs baseline: 4.2989x; 1.0540x over previous
#include <cuda_runtime.h>
#include <cuda_fp16.h>
#include <cstdint>

#define N_TOK   2048
#define D_MODEL 1024
#define D_INT   512
#define NE      8
#define NPAIR   (N_TOK * 2)
#define NPAD    5120              // segments padded to 128-row tiles (40 tiles)
#define KT1     16                // k-tiles fc1 (K=1024, BK=64)
#define KT2     8                 // k-tiles fc2 (K=512)

#define TILE_A      16384         // 128 rows x 128B (fp16, BK=64)
#define TILE_B      32768         // 256 rows x 128B
#define STAGE_BYTES (TILE_A + TILE_B)
#define NSTAGE      3
#define SMEM_SZ     (1024 + NSTAGE * STAGE_BYTES)   // 148480

// ---- scratch (allocation-free: __device__ globals) ----
__device__ int g_poff[NE + 1];
__device__ int g_cnt[NE];
__device__ int g_cur[NE];
__device__ int g_pair[NPAD];
__device__ __align__(16) char g_A1[(size_t)(NPAD / 128) * KT1 * TILE_A];  // 10MB
__device__ __align__(16) char g_B1[(size_t)NE * 4 * KT1 * TILE_B];        // 16MB
__device__ __align__(16) char g_A2[(size_t)(NPAD / 128) * KT2 * TILE_A];  // 5MB
__device__ __align__(16) char g_B2[(size_t)NE * 4 * KT2 * TILE_B];        // 8MB

// ================= asm helpers (sm_90-base PTX only) =================
__device__ __forceinline__ uint32_t smem_u32(const void* p) {
    uint32_t a;
    asm("{ .reg .u64 t; cvta.to.shared.u64 t, %1; cvt.u32.u64 %0, t; }" : "=r"(a) : "l"(p));
    return a;
}
__device__ __forceinline__ void mbar_init(uint32_t a, uint32_t cnt) {
    asm volatile("mbarrier.init.shared::cta.b64 [%0], %1;" :: "r"(a), "r"(cnt) : "memory");
}
__device__ __forceinline__ void mbar_expect_tx(uint32_t a, uint32_t bytes) {
    asm volatile("mbarrier.arrive.expect_tx.shared::cta.b64 _, [%0], %1;"
                 :: "r"(a), "r"(bytes) : "memory");
}
__device__ __forceinline__ void mwait(uint32_t a, uint32_t ph) {
    asm volatile(
        "{\n\t.reg .pred P;\n"
        "W%=:\n\t"
        "mbarrier.try_wait.parity.acquire.cta.shared::cta.b64 P, [%0], %1, 0x989680;\n\t"
        "@P bra D%=;\n\t"
        "bra W%=;\n"
        "D%=:\n\t}"
        :: "r"(a), "r"(ph) : "memory");
}
__device__ __forceinline__ void bulk_g2s(uint32_t dst, const void* src, uint32_t bytes, uint32_t mbar) {
    asm volatile(
        "cp.async.bulk.shared::cluster.global.mbarrier::complete_tx::bytes [%0], [%1], %2, [%3];"
        :: "r"(dst), "l"(src), "r"(bytes), "r"(mbar) : "memory");
}
__device__ __forceinline__ void ldsm4(uint32_t* r, uint32_t a) {
    asm volatile("ldmatrix.sync.aligned.m8n8.x4.shared.b16 {%0,%1,%2,%3}, [%4];"
                 : "=r"(r[0]), "=r"(r[1]), "=r"(r[2]), "=r"(r[3]) : "r"(a));
}
__device__ __forceinline__ void mma_f16(float* d, const uint32_t* a, const uint32_t* b) {
    asm volatile(
        "mma.sync.aligned.m16n8k16.row.col.f32.f16.f16.f32 "
        "{%0,%1,%2,%3}, {%4,%5,%6,%7}, {%8,%9}, {%0,%1,%2,%3};"
        : "+f"(d[0]), "+f"(d[1]), "+f"(d[2]), "+f"(d[3])
        : "r"(a[0]), "r"(a[1]), "r"(a[2]), "r"(a[3]), "r"(b[0]), "r"(b[1]));
}
// SW128 swizzle: 128B rows, 16B chunks (0..7)
__device__ __forceinline__ uint32_t swz128(int row, int chunk) {
    return (uint32_t)(row * 128 + ((chunk ^ (row & 7)) << 4));
}

// ================= fused setup: painit + offsets + scatter =================
__global__ void k_setup(const int* __restrict__ counts, const int* __restrict__ indices) {
    int tid = threadIdx.x;
    if (tid == 0) {
        int o = 0;
        g_poff[0] = 0;
        for (int e = 0; e < NE; e++) {
            int c = counts[e];
            g_cnt[e] = c;
            g_cur[e] = o;
            o += ((c + 127) >> 7) << 7;
            g_poff[e + 1] = o;
        }
    }
    for (int i = tid; i < NPAD; i += 256) g_pair[i] = -1;
    __syncthreads();
    for (int p = tid; p < NPAIR; p += 256) {
        int e = indices[p];
        int pos = atomicAdd(&g_cur[e], 1);
        g_pair[pos] = p;
    }
}

// ================= fused conversion: x + fc1 weights =================
// blocks [0, 2560): x -> g_A1.  blocks [2560, 6656): fc1 w -> g_B1.
__global__ void k_conv(const float* __restrict__ x, const float* __restrict__ w1) {
    int b = blockIdx.x;
    if (b < 2560) {
        int gid = b * 256 + threadIdx.x;     // NPAD * 128
        int s = gid >> 7;
        int k8 = gid & 127;
        char* dst = g_A1 + (size_t)((s >> 7) * KT1 + (k8 >> 3)) * TILE_A + swz128(s & 127, k8 & 7);
        int pr = g_pair[s];
        if (pr < 0) {
            *(uint4*)dst = make_uint4(0, 0, 0, 0);
            return;
        }
        const float* sp = x + (size_t)(pr >> 1) * D_MODEL + k8 * 8;
        float f[8];
        *(float4*)&f[0] = *(const float4*)sp;
        *(float4*)&f[4] = *(const float4*)(sp + 4);
        __half h[8];
#pragma unroll
        for (int i = 0; i < 8; i++) h[i] = __float2half_rn(f[i]);
        *(uint4*)dst = *(uint4*)h;
    } else {
        int gid = (b - 2560) * 256 + threadIdx.x;   // NE*1024*128
        int e = gid >> 17;
        int rem = gid & 131071;
        int n = rem >> 7;
        int k8 = rem & 127;
        int j = n >> 1, g = n & 1;
        const float* sp = w1 + (size_t)e * (2 * D_INT * D_MODEL)
                             + (size_t)(g * D_INT + j) * D_MODEL + k8 * 8;
        float f[8];
        *(float4*)&f[0] = *(const float4*)sp;
        *(float4*)&f[4] = *(const float4*)(sp + 4);
        __half h[8];
#pragma unroll
        for (int i = 0; i < 8; i++) h[i] = __float2half_rn(f[i]);
        char* dst = g_B1 + (size_t)((e * 4 + (n >> 8)) * KT1 + (k8 >> 3)) * TILE_B
                        + swz128(n & 255, k8 & 7);
        *(uint4*)dst = *(uint4*)h;
    }
}

// ================= grouped fp16 MMA GEMM (bulk-copy pipeline, BK=64) =======
// Single-term fp16: C = A*B, fp32 accumulate. BM=128, BN=256, BK=64; 8 warps.
// FC1: grid z=NE handles GEMM; z=NE -> conv_w2 (fc2 weights), z=NE+1 -> zero out.
// FC1 epilogue: a=y*silu(z) -> g_A2. FC2 epilogue: atomicAdd w*val into out.
template<int KT, bool FC1>
__global__ __launch_bounds__(256, 1) void k_mma(
    const char* __restrict__ Abuf, const char* __restrict__ Bbuf,
    const float* __restrict__ wts, float* __restrict__ out,
    const float* __restrict__ w2)
{
    int e = blockIdx.z;
    if (FC1 && e >= NE) {
        int cta = blockIdx.y * 4 + blockIdx.x;      // 0..127
        if (e == NE) {
            // conv_w2: NE*1024*64 = 512K uint4 items
#pragma unroll
            for (int i = 0; i < 16; i++) {
                int gid = i * 32768 + cta * 256 + threadIdx.x;
                int ee = gid >> 16;
                int rem = gid & 65535;
                int n = rem >> 6;
                int k8 = rem & 63;
                const float* sp = w2 + (size_t)ee * (D_MODEL * D_INT) + (size_t)n * D_INT + k8 * 8;
                float f[8];
                *(float4*)&f[0] = *(const float4*)sp;
                *(float4*)&f[4] = *(const float4*)(sp + 4);
                __half h[8];
#pragma unroll
                for (int q = 0; q < 8; q++) h[q] = __float2half_rn(f[q]);
                char* dst = g_B2 + (size_t)((ee * 4 + (n >> 8)) * KT2 + (k8 >> 3)) * TILE_B
                                + swz128(n & 255, k8 & 7);
                *(uint4*)dst = *(uint4*)h;
            }
        } else {
            // zero out: N_TOK*D_MODEL/4 = 512K float4
#pragma unroll
            for (int i = 0; i < 16; i++) {
                int gid = i * 32768 + cta * 256 + threadIdx.x;
                ((float4*)out)[gid] = make_float4(0.f, 0.f, 0.f, 0.f);
            }
        }
        return;
    }

    int cnt = g_cnt[e];
    int mbl = blockIdx.y;
    int rows = cnt - mbl * 128;
    if (rows <= 0) return;
    if (rows > 128) rows = 128;
    int nb = blockIdx.x;
    int arow0 = g_poff[e] + mbl * 128;
    size_t atile = (size_t)((arow0 >> 7) * KT);
    size_t btile = (size_t)((e * 4 + nb) * KT);
    const int n0 = nb * 256;

    extern __shared__ __align__(128) char smem[];
    uint32_t sb = smem_u32(smem);
    int tid = threadIdx.x, lane = tid & 31, wid = tid >> 5;

    if (tid < NSTAGE) mbar_init(sb + tid * 8, 1);
    __syncthreads();
    if (tid == 0) {
        asm volatile("fence.proxy.async.shared::cta;" ::: "memory");
#pragma unroll
        for (int s = 0; s < NSTAGE; s++) {
            mbar_expect_tx(sb + s * 8, STAGE_BYTES);
            uint32_t d = sb + 1024 + s * STAGE_BYTES;
            bulk_g2s(d,          Abuf + (atile + s) * TILE_A, TILE_A, sb + s * 8);
            bulk_g2s(d + TILE_A, Bbuf + (btile + s) * TILE_B, TILE_B, sb + s * 8);
        }
    }

    int wm = wid & 1, wn = wid >> 1;
    int m_off = wm * 64, n_off = wn * 64;

    float acc[4][8][4];
#pragma unroll
    for (int i = 0; i < 4; i++)
#pragma unroll
        for (int j = 0; j < 8; j++)
#pragma unroll
            for (int q = 0; q < 4; q++) acc[i][j][q] = 0.f;

    int arow_l = m_off + (lane & 15);
    int akoff  = lane >> 4;
    int brow_l = n_off + (lane & 7) + ((lane >> 4) << 3);
    int bkoff  = (lane >> 3) & 1;

    int slot = 0, ph = 0;
    for (int kt = 0; kt < KT; kt++) {
        mwait(sb + slot * 8, ph);
        uint32_t base = sb + 1024 + slot * STAGE_BYTES;

#pragma unroll
        for (int ks = 0; ks < 4; ks++) {
            uint32_t ahf[4][4];
            int ak = ks * 2 + akoff;
#pragma unroll
            for (int mf = 0; mf < 4; mf++)
                ldsm4(ahf[mf], base + swz128(arow_l + mf * 16, ak));
            int bk = ks * 2 + bkoff;
#pragma unroll
            for (int ng = 0; ng < 4; ng++) {
                uint32_t bf[4];
                ldsm4(bf, base + TILE_A + swz128(brow_l + ng * 16, bk));
#pragma unroll
                for (int mf = 0; mf < 4; mf++) {
                    mma_f16(acc[mf][2 * ng],     ahf[mf], &bf[0]);
                    mma_f16(acc[mf][2 * ng + 1], ahf[mf], &bf[2]);
                }
            }
        }
        __syncthreads();
        if (tid == 0 && kt + NSTAGE < KT) {
            mbar_expect_tx(sb + slot * 8, STAGE_BYTES);
            bulk_g2s(base,          Abuf + (atile + kt + NSTAGE) * TILE_A, TILE_A, sb + slot * 8);
            bulk_g2s(base + TILE_A, Bbuf + (btile + kt + NSTAGE) * TILE_B, TILE_B, sb + slot * 8);
        }
        if (++slot == NSTAGE) { slot = 0; ph ^= 1; }
    }

    // ---- epilogue ----
    int rq = lane >> 2, cq = lane & 3;
#pragma unroll
    for (int mf = 0; mf < 4; mf++) {
#pragma unroll
        for (int half = 0; half < 2; half++) {
            int mloc = m_off + mf * 16 + rq + half * 8;
            if (mloc >= rows) continue;
            int s = arow0 + mloc;
            if (FC1) {
                int r = s & 127;
                size_t trow = (size_t)(s >> 7) * KT2;
#pragma unroll
                for (int nt = 0; nt < 8; nt++) {
                    float y = acc[mf][nt][half * 2];
                    float z = acc[mf][nt][half * 2 + 1];
                    float a = y * z * (1.f / (1.f + __expf(-z)));
                    int j = ((n0 + n_off + nt * 8) >> 1) + cq;
                    char* p = g_A2 + (trow + (j >> 6)) * TILE_A
                                  + swz128(r, (j >> 3) & 7) + (j & 7) * 2;
                    *(__half*)p = __float2half_rn(a);
                }
            } else {
                int pr = g_pair[s];
                float w = wts[pr];
                float* ob = out + (size_t)(pr >> 1) * D_MODEL;
#pragma unroll
                for (int nt = 0; nt < 8; nt++) {
                    int nc = n0 + n_off + nt * 8 + cq * 2;
                    atomicAdd(ob + nc,     w * acc[mf][nt][half * 2]);
                    atomicAdd(ob + nc + 1, w * acc[mf][nt][half * 2 + 1]);
                }
            }
        }
    }
}

// ================= host =================
extern "C" void kernel_launch(void* const* d_in, const int* in_sizes, int n_in,
                              void* d_out, int out_size) {
    const float* x      = (const float*)d_in[0];
    const float* wts    = (const float*)d_in[1];
    const int*   idx    = (const int*)d_in[2];
    const int*   counts = (const int*)d_in[3];
    const float* fc1w   = (const float*)d_in[4];
    const float* fc2w   = (const float*)d_in[5];
    float* out = (float*)d_out;

    cudaFuncSetAttribute(k_mma<KT1, true>,
                         cudaFuncAttributeMaxDynamicSharedMemorySize, SMEM_SZ);
    cudaFuncSetAttribute(k_mma<KT2, false>,
                         cudaFuncAttributeMaxDynamicSharedMemorySize, SMEM_SZ);

    void *pA1, *pB1, *pA2, *pB2;
    cudaGetSymbolAddress(&pA1, g_A1);
    cudaGetSymbolAddress(&pB1, g_B1);
    cudaGetSymbolAddress(&pA2, g_A2);
    cudaGetSymbolAddress(&pB2, g_B2);

    k_setup<<<1, 256>>>(counts, idx);
    k_conv<<<6656, 256>>>(x, fc1w);

    dim3 g1(4, 32, NE + 2);   // z=NE: conv_w2, z=NE+1: zero(out)
    k_mma<KT1, true><<<g1, 256, SMEM_SZ>>>((const char*)pA1, (const char*)pB1,
                                           wts, out, fc2w);
    dim3 g2(4, 32, NE);
    k_mma<KT2, false><<<g2, 256, SMEM_SZ>>>((const char*)pA2, (const char*)pB2,
                                            wts, out, fc2w);
}

// round 7
// speedup vs baseline: 4.3736x; 1.0174x over previous
#include <cuda_runtime.h>
#include <cuda_fp16.h>
#include <cstdint>

#define N_TOK   2048
#define D_MODEL 1024
#define D_INT   512
#define NE      8
#define NPAIR   (N_TOK * 2)
#define NPAD    5120              // segments padded to 128-row tiles (40 tiles)
#define KT1     16                // k-tiles fc1 (K=1024, BK=64)
#define KT2     8                 // k-tiles fc2 (K=512)

#define TILE_A      16384         // 128 rows x 128B (fp16, BK=64)
#define TILE_B      16384         // 128 rows x 128B
#define STAGE_BYTES (TILE_A + TILE_B)
#define NSTAGE      3
#define SMEM_SZ     (1024 + NSTAGE * STAGE_BYTES)   // 99328 -> 2 CTAs/SM

// ---- scratch (allocation-free: __device__ globals) ----
__device__ int g_poff[NE + 1];
__device__ int g_cnt[NE];
__device__ int g_cur[NE];
__device__ int g_pair[NPAD];
__device__ __align__(16) char g_A1[(size_t)(NPAD / 128) * KT1 * TILE_A];  // 10MB
__device__ __align__(16) char g_B1[(size_t)NE * 8 * KT1 * TILE_B];        // 16MB
__device__ __align__(16) char g_A2[(size_t)(NPAD / 128) * KT2 * TILE_A];  // 5MB
__device__ __align__(16) char g_B2[(size_t)NE * 8 * KT2 * TILE_B];        // 8MB

// ================= asm helpers (sm_90-base PTX only) =================
__device__ __forceinline__ uint32_t smem_u32(const void* p) {
    uint32_t a;
    asm("{ .reg .u64 t; cvta.to.shared.u64 t, %1; cvt.u32.u64 %0, t; }" : "=r"(a) : "l"(p));
    return a;
}
__device__ __forceinline__ void mbar_init(uint32_t a, uint32_t cnt) {
    asm volatile("mbarrier.init.shared::cta.b64 [%0], %1;" :: "r"(a), "r"(cnt) : "memory");
}
__device__ __forceinline__ void mbar_expect_tx(uint32_t a, uint32_t bytes) {
    asm volatile("mbarrier.arrive.expect_tx.shared::cta.b64 _, [%0], %1;"
                 :: "r"(a), "r"(bytes) : "memory");
}
__device__ __forceinline__ void mwait(uint32_t a, uint32_t ph) {
    asm volatile(
        "{\n\t.reg .pred P;\n"
        "W%=:\n\t"
        "mbarrier.try_wait.parity.acquire.cta.shared::cta.b64 P, [%0], %1, 0x989680;\n\t"
        "@P bra D%=;\n\t"
        "bra W%=;\n"
        "D%=:\n\t}"
        :: "r"(a), "r"(ph) : "memory");
}
__device__ __forceinline__ void bulk_g2s(uint32_t dst, const void* src, uint32_t bytes, uint32_t mbar) {
    asm volatile(
        "cp.async.bulk.shared::cluster.global.mbarrier::complete_tx::bytes [%0], [%1], %2, [%3];"
        :: "r"(dst), "l"(src), "r"(bytes), "r"(mbar) : "memory");
}
__device__ __forceinline__ void ldsm4(uint32_t* r, uint32_t a) {
    asm volatile("ldmatrix.sync.aligned.m8n8.x4.shared.b16 {%0,%1,%2,%3}, [%4];"
                 : "=r"(r[0]), "=r"(r[1]), "=r"(r[2]), "=r"(r[3]) : "r"(a));
}
__device__ __forceinline__ void mma_f16(float* d, const uint32_t* a, const uint32_t* b) {
    asm volatile(
        "mma.sync.aligned.m16n8k16.row.col.f32.f16.f16.f32 "
        "{%0,%1,%2,%3}, {%4,%5,%6,%7}, {%8,%9}, {%0,%1,%2,%3};"
        : "+f"(d[0]), "+f"(d[1]), "+f"(d[2]), "+f"(d[3])
        : "r"(a[0]), "r"(a[1]), "r"(a[2]), "r"(a[3]), "r"(b[0]), "r"(b[1]));
}
// SW128 swizzle: 128B rows, 16B chunks (0..7)
__device__ __forceinline__ uint32_t swz128(int row, int chunk) {
    return (uint32_t)(row * 128 + ((chunk ^ (row & 7)) << 4));
}

// ================= fused setup =================
__global__ void k_setup(const int* __restrict__ counts, const int* __restrict__ indices) {
    int tid = threadIdx.x;
    if (tid == 0) {
        int o = 0;
        g_poff[0] = 0;
        for (int e = 0; e < NE; e++) {
            int c = counts[e];
            g_cnt[e] = c;
            g_cur[e] = o;
            o += ((c + 127) >> 7) << 7;
            g_poff[e + 1] = o;
        }
    }
    for (int i = tid; i < NPAD; i += 256) g_pair[i] = -1;
    __syncthreads();
    for (int p = tid; p < NPAIR; p += 256) {
        int e = indices[p];
        int pos = atomicAdd(&g_cur[e], 1);
        g_pair[pos] = p;
    }
}

// ================= fused conversion: x + fc1 weights =================
__global__ void k_conv(const float* __restrict__ x, const float* __restrict__ w1) {
    int b = blockIdx.x;
    if (b < 2560) {
        int gid = b * 256 + threadIdx.x;     // NPAD * 128
        int s = gid >> 7;
        int k8 = gid & 127;
        char* dst = g_A1 + (size_t)((s >> 7) * KT1 + (k8 >> 3)) * TILE_A + swz128(s & 127, k8 & 7);
        int pr = g_pair[s];
        if (pr < 0) {
            *(uint4*)dst = make_uint4(0, 0, 0, 0);
            return;
        }
        const float* sp = x + (size_t)(pr >> 1) * D_MODEL + k8 * 8;
        float f[8];
        *(float4*)&f[0] = *(const float4*)sp;
        *(float4*)&f[4] = *(const float4*)(sp + 4);
        __half h[8];
#pragma unroll
        for (int i = 0; i < 8; i++) h[i] = __float2half_rn(f[i]);
        *(uint4*)dst = *(uint4*)h;
    } else {
        int gid = (b - 2560) * 256 + threadIdx.x;   // NE*1024*128
        int e = gid >> 17;
        int rem = gid & 131071;
        int n = rem >> 7;
        int k8 = rem & 127;
        int j = n >> 1, g = n & 1;
        const float* sp = w1 + (size_t)e * (2 * D_INT * D_MODEL)
                             + (size_t)(g * D_INT + j) * D_MODEL + k8 * 8;
        float f[8];
        *(float4*)&f[0] = *(const float4*)sp;
        *(float4*)&f[4] = *(const float4*)(sp + 4);
        __half h[8];
#pragma unroll
        for (int i = 0; i < 8; i++) h[i] = __float2half_rn(f[i]);
        char* dst = g_B1 + (size_t)((e * 8 + (n >> 7)) * KT1 + (k8 >> 3)) * TILE_B
                        + swz128(n & 127, k8 & 7);
        *(uint4*)dst = *(uint4*)h;
    }
}

// ================= grouped fp16 MMA GEMM (BM=128, BN=128, BK=64) ===========
// 8 warps (2m x 4n), warp tile 64x32. 2 CTAs/SM.
// FC1: z=NE -> conv_w2, z=NE+1 -> zero(out). Epilogue fc1: silu-gate -> g_A2.
// FC2 epilogue: atomicAdd w*val into out.
template<int KT, bool FC1>
__global__ __launch_bounds__(256, 2) void k_mma(
    const char* __restrict__ Abuf, const char* __restrict__ Bbuf,
    const float* __restrict__ wts, float* __restrict__ out,
    const float* __restrict__ w2)
{
    int e = blockIdx.z;
    if (FC1 && e >= NE) {
        int cta = blockIdx.y * 8 + blockIdx.x;      // 0..255
        if (e == NE) {
            // conv_w2: NE*1024*64 = 512K uint4 items over 256 CTAs
#pragma unroll
            for (int i = 0; i < 8; i++) {
                int gid = i * 65536 + cta * 256 + threadIdx.x;
                int ee = gid >> 16;
                int rem = gid & 65535;
                int n = rem >> 6;
                int k8 = rem & 63;
                const float* sp = w2 + (size_t)ee * (D_MODEL * D_INT) + (size_t)n * D_INT + k8 * 8;
                float f[8];
                *(float4*)&f[0] = *(const float4*)sp;
                *(float4*)&f[4] = *(const float4*)(sp + 4);
                __half h[8];
#pragma unroll
                for (int q = 0; q < 8; q++) h[q] = __float2half_rn(f[q]);
                char* dst = g_B2 + (size_t)((ee * 8 + (n >> 7)) * KT2 + (k8 >> 3)) * TILE_B
                                + swz128(n & 127, k8 & 7);
                *(uint4*)dst = *(uint4*)h;
            }
        } else {
            // zero out: 512K float4 over 256 CTAs
#pragma unroll
            for (int i = 0; i < 8; i++) {
                int gid = i * 65536 + cta * 256 + threadIdx.x;
                ((float4*)out)[gid] = make_float4(0.f, 0.f, 0.f, 0.f);
            }
        }
        return;
    }

    int cnt = g_cnt[e];
    int mbl = blockIdx.y;
    int rows = cnt - mbl * 128;
    if (rows <= 0) return;
    if (rows > 128) rows = 128;
    int nb = blockIdx.x;
    int arow0 = g_poff[e] + mbl * 128;
    size_t atile = (size_t)((arow0 >> 7) * KT);
    size_t btile = (size_t)((e * 8 + nb) * KT);
    const int n0 = nb * 128;

    extern __shared__ __align__(128) char smem[];
    uint32_t sb = smem_u32(smem);
    int tid = threadIdx.x, lane = tid & 31, wid = tid >> 5;

    if (tid < NSTAGE) mbar_init(sb + tid * 8, 1);
    __syncthreads();
    if (tid == 0) {
        asm volatile("fence.proxy.async.shared::cta;" ::: "memory");
#pragma unroll
        for (int s = 0; s < NSTAGE; s++) {
            mbar_expect_tx(sb + s * 8, STAGE_BYTES);
            uint32_t d = sb + 1024 + s * STAGE_BYTES;
            bulk_g2s(d,          Abuf + (atile + s) * TILE_A, TILE_A, sb + s * 8);
            bulk_g2s(d + TILE_A, Bbuf + (btile + s) * TILE_B, TILE_B, sb + s * 8);
        }
    }

    int wm = wid & 1, wn = wid >> 1;
    int m_off = wm * 64, n_off = wn * 32;

    float acc[4][4][4];
#pragma unroll
    for (int i = 0; i < 4; i++)
#pragma unroll
        for (int j = 0; j < 4; j++)
#pragma unroll
            for (int q = 0; q < 4; q++) acc[i][j][q] = 0.f;

    int arow_l = m_off + (lane & 15);
    int akoff  = lane >> 4;
    int brow_l = n_off + (lane & 7) + ((lane >> 4) << 3);
    int bkoff  = (lane >> 3) & 1;

    int slot = 0, ph = 0;
    for (int kt = 0; kt < KT; kt++) {
        mwait(sb + slot * 8, ph);
        uint32_t base = sb + 1024 + slot * STAGE_BYTES;

#pragma unroll
        for (int ks = 0; ks < 4; ks++) {
            uint32_t ahf[4][4];
            int ak = ks * 2 + akoff;
#pragma unroll
            for (int mf = 0; mf < 4; mf++)
                ldsm4(ahf[mf], base + swz128(arow_l + mf * 16, ak));
            int bk = ks * 2 + bkoff;
#pragma unroll
            for (int ng = 0; ng < 2; ng++) {
                uint32_t bf[4];
                ldsm4(bf, base + TILE_A + swz128(brow_l + ng * 16, bk));
#pragma unroll
                for (int mf = 0; mf < 4; mf++) {
                    mma_f16(acc[mf][2 * ng],     ahf[mf], &bf[0]);
                    mma_f16(acc[mf][2 * ng + 1], ahf[mf], &bf[2]);
                }
            }
        }
        __syncthreads();
        if (tid == 0 && kt + NSTAGE < KT) {
            mbar_expect_tx(sb + slot * 8, STAGE_BYTES);
            bulk_g2s(base,          Abuf + (atile + kt + NSTAGE) * TILE_A, TILE_A, sb + slot * 8);
            bulk_g2s(base + TILE_A, Bbuf + (btile + kt + NSTAGE) * TILE_B, TILE_B, sb + slot * 8);
        }
        if (++slot == NSTAGE) { slot = 0; ph ^= 1; }
    }

    // ---- epilogue ----
    int rq = lane >> 2, cq = lane & 3;
#pragma unroll
    for (int mf = 0; mf < 4; mf++) {
#pragma unroll
        for (int half = 0; half < 2; half++) {
            int mloc = m_off + mf * 16 + rq + half * 8;
            if (mloc >= rows) continue;
            int s = arow0 + mloc;
            if (FC1) {
                int r = s & 127;
                size_t trow = (size_t)(s >> 7) * KT2;
#pragma unroll
                for (int nt = 0; nt < 4; nt++) {
                    float y = acc[mf][nt][half * 2];
                    float z = acc[mf][nt][half * 2 + 1];
                    float a = y * z * (1.f / (1.f + __expf(-z)));
                    int j = ((n0 + n_off + nt * 8) >> 1) + cq;
                    char* p = g_A2 + (trow + (j >> 6)) * TILE_A
                                  + swz128(r, (j >> 3) & 7) + (j & 7) * 2;
                    *(__half*)p = __float2half_rn(a);
                }
            } else {
                int pr = g_pair[s];
                float w = wts[pr];
                float* ob = out + (size_t)(pr >> 1) * D_MODEL;
#pragma unroll
                for (int nt = 0; nt < 4; nt++) {
                    int nc = n0 + n_off + nt * 8 + cq * 2;
                    atomicAdd(ob + nc,     w * acc[mf][nt][half * 2]);
                    atomicAdd(ob + nc + 1, w * acc[mf][nt][half * 2 + 1]);
                }
            }
        }
    }
}

// ================= host =================
extern "C" void kernel_launch(void* const* d_in, const int* in_sizes, int n_in,
                              void* d_out, int out_size) {
    const float* x      = (const float*)d_in[0];
    const float* wts    = (const float*)d_in[1];
    const int*   idx    = (const int*)d_in[2];
    const int*   counts = (const int*)d_in[3];
    const float* fc1w   = (const float*)d_in[4];
    const float* fc2w   = (const float*)d_in[5];
    float* out = (float*)d_out;

    cudaFuncSetAttribute(k_mma<KT1, true>,
                         cudaFuncAttributeMaxDynamicSharedMemorySize, SMEM_SZ);
    cudaFuncSetAttribute(k_mma<KT2, false>,
                         cudaFuncAttributeMaxDynamicSharedMemorySize, SMEM_SZ);

    void *pA1, *pB1, *pA2, *pB2;
    cudaGetSymbolAddress(&pA1, g_A1);
    cudaGetSymbolAddress(&pB1, g_B1);
    cudaGetSymbolAddress(&pA2, g_A2);
    cudaGetSymbolAddress(&pB2, g_B2);

    k_setup<<<1, 256>>>(counts, idx);
    k_conv<<<6656, 256>>>(x, fc1w);

    dim3 g1(8, 32, NE + 2);   // z=NE: conv_w2, z=NE+1: zero(out)
    k_mma<KT1, true><<<g1, 256, SMEM_SZ>>>((const char*)pA1, (const char*)pB1,
                                           wts, out, fc2w);
    dim3 g2(8, 32, NE);
    k_mma<KT2, false><<<g2, 256, SMEM_SZ>>>((const char*)pA2, (const char*)pB2,
                                            wts, out, fc2w);
}